// round 3
// baseline (speedup 1.0000x reference)
#include <cuda_runtime.h>
#include <cuda_bf16.h>

// Problem shapes (fixed by the dataset)
#define BB   128            // batch
#define NN   256            // boxes per batch
#define HH   256
#define WW   256
#define HW   (HH * WW)      // 65536

// Packed accumulator: bits [0,48) = sum(loss * 2^32), bits [48,64) = count.
// Max sum = 32768 * 2^32 = 2^47 < 2^48; max count = 32768 < 2^16. No overflow.
__device__ unsigned long long g_acc    = 0ULL;
__device__ unsigned int       g_arrive = 0u;

__global__ __launch_bounds__(NN) void iou_loss_fused(
    const float* __restrict__ out,      // [B, 2, H, W]
    const float* __restrict__ target,   // [B, N, 2]
    const int*   __restrict__ ind,      // [B, N]
    const int*   __restrict__ mask,     // [B, N] (bool promoted to int32)
    float*       __restrict__ d_out)
{
    const int b   = blockIdx.x;
    const int n   = threadIdx.x;
    const int idx = b * NN + n;

    // Front-batch all independent loads.
    const int    mk = mask[idx];
    const int    id = ind[idx];
    const float2 tg = reinterpret_cast<const float2*>(target)[idx];

    // Unconditional gather (id always in [0, HW)) — no divergence.
    const float* base = out + (size_t)b * 2 * HW;
    const float  dx   = __ldg(base + id);        // channel 0
    const float  dy   = __ldg(base + HW + id);   // channel 1

    const float tx = tg.x, ty = tg.y;
    const float x  = (float)(id & (WW - 1));
    const float y  = (float)(id >> 8);

    // trunc toward zero, matching torch .int() / jnp.trunc
    const float gx = truncf(x - tx * 0.5f);
    const float gy = truncf(y - ty * 0.5f);
    const float px = truncf(x - dx * 0.5f);
    const float py = truncf(y - dy * 0.5f);

    const float g_x1 = gx - tx * 0.5f, g_x2 = gx + tx * 0.5f;
    const float g_y1 = gy - ty * 0.5f, g_y2 = gy + ty * 0.5f;
    const float d_x1 = px - dx * 0.5f, d_x2 = px + dx * 0.5f;
    const float d_y1 = py - dy * 0.5f, d_y2 = py + dy * 0.5f;

    const float iw = fmaxf(fminf(g_x2, d_x2) - fmaxf(g_x1, d_x1), 0.0f);
    const float ih = fmaxf(fminf(g_y2, d_y2) - fmaxf(g_y1, d_y1), 0.0f);
    const float inter = iw * ih;

    const float w1 = g_x2 - g_x1, h1 = g_y2 - g_y1;
    const float w2 = d_x2 - d_x1, h2 = d_y2 - d_y1;
    const float uni = w1 * h1 + 1e-16f + w2 * h2 - inter;

    const float loss = 1.0f - inter / uni;   // in [0, 1]

    // Pack: quantized loss (2^32 fixed point) + mask count at bit 48.
    unsigned long long val = 0ULL;
    if (mk != 0)
        val = (unsigned long long)(loss * 4294967296.0f) + (1ULL << 48);

    // ── warp reduction (integer: exact, order-independent) ──
    #pragma unroll
    for (int off = 16; off > 0; off >>= 1)
        val += __shfl_down_sync(0xFFFFFFFFu, val, off);

    __shared__ unsigned long long s_val[NN / 32];
    const int lane = n & 31, warp = n >> 5;
    if (lane == 0) s_val[warp] = val;
    __syncthreads();

    if (n == 0) {
        unsigned long long v = 0ULL;
        #pragma unroll
        for (int i = 0; i < NN / 32; i++) v += s_val[i];

        // One relaxed 64-bit atomic per block into the packed accumulator.
        atomicAdd(&g_acc, v);

        // acq_rel RMW ticket: release orders my g_acc add before my arrive;
        // acquire on the RMW chain makes all prior blocks' adds visible.
        unsigned ticket;
        asm volatile("atom.global.add.acq_rel.gpu.u32 %0, [%1], %2;"
                     : "=r"(ticket) : "l"(&g_arrive), "r"(1u) : "memory");

        if (ticket == BB - 1) {
            unsigned long long total;
            asm volatile("ld.global.relaxed.gpu.b64 %0, [%1];"
                         : "=l"(total) : "l"(&g_acc) : "memory");
            const float sumf = (float)(total & 0xFFFFFFFFFFFFULL)
                               * (1.0f / 4294967296.0f);
            const float cnt  = (float)(unsigned)(total >> 48);
            d_out[0] = sumf / (4.0f * cnt + 0.0001f);
            // reset for next graph replay
            asm volatile("st.global.relaxed.gpu.b64 [%0], %1;"
                         :: "l"(&g_acc), "l"(0ULL) : "memory");
            asm volatile("st.global.relaxed.gpu.b32 [%0], %1;"
                         :: "l"(&g_arrive), "r"(0u) : "memory");
        }
    }
}

extern "C" void kernel_launch(void* const* d_in, const int* in_sizes, int n_in,
                              void* d_out, int out_size)
{
    const float* out_map = (const float*)d_in[0];  // [128,2,256,256] f32
    const float* target  = (const float*)d_in[1];  // [128,256,2]     f32
    const int*   ind     = (const int*)  d_in[2];  // [128,256]       i32
    const int*   mask    = (const int*)  d_in[3];  // [128,256]       i32 (bool)
    float*       outp    = (float*)d_out;

    iou_loss_fused<<<BB, NN>>>(out_map, target, ind, mask, outp);
}

// round 4
// speedup vs baseline: 1.0257x; 1.0257x over previous
#include <cuda_runtime.h>
#include <cuda_bf16.h>

// Problem shapes (fixed by the dataset)
#define BB    128           // batch
#define NN    256           // boxes per batch
#define WW    256
#define HW    (256 * 256)   // 65536
#define TOTAL (BB * NN)     // 32768

#define NBLK  32
#define NTHR  256
#define VPT   4             // elements per thread: 32*256*4 = 32768

// Packed accumulator: bits [0,48) = sum(loss * 2^32), bits [48,64) = count.
__device__ unsigned long long g_acc    = 0ULL;
__device__ unsigned int       g_arrive = 0u;

__global__ __launch_bounds__(NTHR) void iou_loss_fused(
    const float* __restrict__ out,      // [B, 2, H, W]
    const float* __restrict__ target,   // [B, N, 2]
    const int*   __restrict__ ind,      // [B, N]
    const int*   __restrict__ mask,     // [B, N] (bool promoted to int32)
    float*       __restrict__ d_out)
{
    const int t    = threadIdx.x;
    const int vid  = blockIdx.x * NTHR + t;   // vector id, 0..8191
    const int idx0 = vid * VPT;               // first element

    // ── front-batched wide loads (high MLP, all independent) ──
    const int4   mk4 = reinterpret_cast<const int4*>(mask)[vid];
    const int4   id4 = reinterpret_cast<const int4*>(ind)[vid];
    const float4 tg0 = reinterpret_cast<const float4*>(target)[vid * 2 + 0];
    const float4 tg1 = reinterpret_cast<const float4*>(target)[vid * 2 + 1];

    const int   mks[VPT] = { mk4.x, mk4.y, mk4.z, mk4.w };
    const int   ids[VPT] = { id4.x, id4.y, id4.z, id4.w };
    const float txs[VPT] = { tg0.x, tg0.z, tg1.x, tg1.z };
    const float tys[VPT] = { tg0.y, tg0.w, tg1.y, tg1.w };

    // conditional gathers (halve DRAM line traffic); issue all before compute
    float dxs[VPT], dys[VPT];
    #pragma unroll
    for (int i = 0; i < VPT; i++) {
        const int b = (idx0 + i) >> 8;        // element / NN
        const float* base = out + (size_t)b * 2 * HW;
        dxs[i] = 0.0f; dys[i] = 0.0f;
        if (mks[i] != 0) {
            dxs[i] = __ldg(base + ids[i]);
            dys[i] = __ldg(base + HW + ids[i]);
        }
    }

    unsigned long long val = 0ULL;
    #pragma unroll
    for (int i = 0; i < VPT; i++) {
        if (mks[i] == 0) continue;
        const int   id = ids[i];
        const float tx = txs[i], ty = tys[i];
        const float dx = dxs[i], dy = dys[i];
        const float x  = (float)(id & (WW - 1));
        const float y  = (float)(id >> 8);

        const float gx = truncf(x - tx * 0.5f);
        const float gy = truncf(y - ty * 0.5f);
        const float px = truncf(x - dx * 0.5f);
        const float py = truncf(y - dy * 0.5f);

        const float g_x1 = gx - tx * 0.5f, g_x2 = gx + tx * 0.5f;
        const float g_y1 = gy - ty * 0.5f, g_y2 = gy + ty * 0.5f;
        const float d_x1 = px - dx * 0.5f, d_x2 = px + dx * 0.5f;
        const float d_y1 = py - dy * 0.5f, d_y2 = py + dy * 0.5f;

        const float iw = fmaxf(fminf(g_x2, d_x2) - fmaxf(g_x1, d_x1), 0.0f);
        const float ih = fmaxf(fminf(g_y2, d_y2) - fmaxf(g_y1, d_y1), 0.0f);
        const float inter = iw * ih;

        const float w1 = g_x2 - g_x1, h1 = g_y2 - g_y1;
        const float w2 = d_x2 - d_x1, h2 = d_y2 - d_y1;
        const float uni = w1 * h1 + 1e-16f + w2 * h2 - inter;

        const float loss = 1.0f - inter / uni;   // in [0, 1]
        val += (unsigned long long)(loss * 4294967296.0f) + (1ULL << 48);
    }

    // ── integer warp/block reduction (exact, order-independent) ──
    #pragma unroll
    for (int off = 16; off > 0; off >>= 1)
        val += __shfl_down_sync(0xFFFFFFFFu, val, off);

    __shared__ unsigned long long s_val[NTHR / 32];
    const int lane = t & 31, warp = t >> 5;
    if (lane == 0) s_val[warp] = val;
    __syncthreads();

    if (t == 0) {
        unsigned long long v = 0ULL;
        #pragma unroll
        for (int i = 0; i < NTHR / 32; i++) v += s_val[i];

        atomicAdd(&g_acc, v);

        unsigned ticket;
        asm volatile("atom.global.add.acq_rel.gpu.u32 %0, [%1], %2;"
                     : "=r"(ticket) : "l"(&g_arrive), "r"(1u) : "memory");

        if (ticket == NBLK - 1) {
            unsigned long long total;
            asm volatile("ld.global.relaxed.gpu.b64 %0, [%1];"
                         : "=l"(total) : "l"(&g_acc) : "memory");
            const float sumf = (float)(total & 0xFFFFFFFFFFFFULL)
                               * (1.0f / 4294967296.0f);
            const float cnt  = (float)(unsigned)(total >> 48);
            d_out[0] = sumf / (4.0f * cnt + 0.0001f);
            asm volatile("st.global.relaxed.gpu.b64 [%0], %1;"
                         :: "l"(&g_acc), "l"(0ULL) : "memory");
            asm volatile("st.global.relaxed.gpu.b32 [%0], %1;"
                         :: "l"(&g_arrive), "r"(0u) : "memory");
        }
    }
}

extern "C" void kernel_launch(void* const* d_in, const int* in_sizes, int n_in,
                              void* d_out, int out_size)
{
    const float* out_map = (const float*)d_in[0];  // [128,2,256,256] f32
    const float* target  = (const float*)d_in[1];  // [128,256,2]     f32
    const int*   ind     = (const int*)  d_in[2];  // [128,256]       i32
    const int*   mask    = (const int*)  d_in[3];  // [128,256]       i32 (bool)
    float*       outp    = (float*)d_out;

    iou_loss_fused<<<NBLK, NTHR>>>(out_map, target, ind, mask, outp);
}

// round 5
// speedup vs baseline: 1.3413x; 1.3077x over previous
#include <cuda_runtime.h>
#include <cuda_bf16.h>

// Problem shapes (fixed by the dataset)
#define BB   128            // batch = grid
#define NN   256            // boxes per batch = block
#define WW   256
#define HW   (256 * 256)    // 65536

// Single packed accumulator:
//   bits [0,40)  : sum(loss * 2^24)   (max 32768 * 2^24 = 2^39)
//   bits [40,56) : masked element count (max 32768 < 2^16)
//   bits [56,64) : block arrival count  (128 <= 255)
// One atomicAdd per block; atomic total order on this one location means the
// block whose post-add value has arrival==BB holds the complete sum. No fence,
// no second counter, no reload.
__device__ unsigned long long g_acc = 0ULL;

#define Q_SCALE   16777216.0f            // 2^24
#define CNT_ONE   (1ULL << 40)
#define BLK_ONE   (1ULL << 56)
#define SUM_MASK  ((1ULL << 40) - 1)

__global__ __launch_bounds__(NN) void iou_loss_fused(
    const float* __restrict__ out,      // [B, 2, H, W]
    const float* __restrict__ target,   // [B, N, 2]
    const int*   __restrict__ ind,      // [B, N]
    const int*   __restrict__ mask,     // [B, N] (bool promoted to int32)
    float*       __restrict__ d_out)
{
    const int b   = blockIdx.x;
    const int n   = threadIdx.x;
    const int idx = b * NN + n;

    // front-batched independent loads
    const int    mk = mask[idx];
    const int    id = ind[idx];
    const float2 tg = reinterpret_cast<const float2*>(target)[idx];

    unsigned long long val = 0ULL;

    if (mk != 0) {
        const float* base = out + (unsigned)b * (2 * HW);
        const float dx = __ldg(base + id);        // channel 0
        const float dy = __ldg(base + HW + id);   // channel 1

        const float tx = tg.x, ty = tg.y;
        const float x  = (float)(id & (WW - 1));
        const float y  = (float)(id >> 8);

        // trunc toward zero, matching torch .int() / jnp.trunc
        const float gx = truncf(x - tx * 0.5f);
        const float gy = truncf(y - ty * 0.5f);
        const float px = truncf(x - dx * 0.5f);
        const float py = truncf(y - dy * 0.5f);

        const float g_x1 = gx - tx * 0.5f, g_x2 = gx + tx * 0.5f;
        const float g_y1 = gy - ty * 0.5f, g_y2 = gy + ty * 0.5f;
        const float d_x1 = px - dx * 0.5f, d_x2 = px + dx * 0.5f;
        const float d_y1 = py - dy * 0.5f, d_y2 = py + dy * 0.5f;

        const float iw = fmaxf(fminf(g_x2, d_x2) - fmaxf(g_x1, d_x1), 0.0f);
        const float ih = fmaxf(fminf(g_y2, d_y2) - fmaxf(g_y1, d_y1), 0.0f);
        const float inter = iw * ih;

        const float w1 = g_x2 - g_x1, h1 = g_y2 - g_y1;
        const float w2 = d_x2 - d_x1, h2 = d_y2 - d_y1;
        const float uni = w1 * h1 + 1e-16f + w2 * h2 - inter;

        // loss in [0,1]; clamp against ulp overshoot before unsigned cast
        const float loss = fmaxf(1.0f - inter / uni, 0.0f);
        val = (unsigned long long)(loss * Q_SCALE) + CNT_ONE;
    }

    // ── integer warp/block reduction (exact, order-independent) ──
    #pragma unroll
    for (int off = 16; off > 0; off >>= 1)
        val += __shfl_down_sync(0xFFFFFFFFu, val, off);

    __shared__ unsigned long long s_val[NN / 32];
    const int lane = n & 31, warp = n >> 5;
    if (lane == 0) s_val[warp] = val;
    __syncthreads();

    if (n == 0) {
        unsigned long long v = BLK_ONE;   // this block's arrival mark
        #pragma unroll
        for (int i = 0; i < NN / 32; i++) v += s_val[i];

        const unsigned long long total = atomicAdd(&g_acc, v) + v;

        if ((unsigned)(total >> 56) == BB) {
            // we observed every block's contribution — finalize
            const float sumf = (float)(total & SUM_MASK) * (1.0f / Q_SCALE);
            const float cnt  = (float)(unsigned)((total >> 40) & 0xFFFF);
            d_out[0] = sumf / (4.0f * cnt + 0.0001f);
            g_acc = 0ULL;                 // reset for next graph replay
        }
    }
}

extern "C" void kernel_launch(void* const* d_in, const int* in_sizes, int n_in,
                              void* d_out, int out_size)
{
    const float* out_map = (const float*)d_in[0];  // [128,2,256,256] f32
    const float* target  = (const float*)d_in[1];  // [128,256,2]     f32
    const int*   ind     = (const int*)  d_in[2];  // [128,256]       i32
    const int*   mask    = (const int*)  d_in[3];  // [128,256]       i32 (bool)
    float*       outp    = (float*)d_out;

    iou_loss_fused<<<BB, NN>>>(out_map, target, ind, mask, outp);
}